// round 14
// baseline (speedup 1.0000x reference)
#include <cuda_runtime.h>
#include <cuda_fp16.h>
#include <cstdint>

#define LL 4096
#define DM 384
#define DI 768
#define DS 16
#define DR 24
#define NB 2
#define XW (DR + 2*DS)   // 56

// ----------------------------- scratch (device globals) -----------------------------
__device__ float g_xc   [2][NB][LL][DI];     // after causal conv + silu (fp32)
__device__ float g_xdbl [2][NB][LL][XW];     // x-proj output (dt | B | C)
__device__ float g_delta[2][NB][LL][DI];     // softplus(dt@dtw+b)
__device__ float g_Bc   [2][NB][LL/4][DS][4];
__device__ float g_Cc   [2][NB][LL/4][DS][4];
__device__ float g_yc   [NB][LL][2*DM];
__device__ float g_glu  [NB][LL][DM];
__device__ float2 g_part[NB][64];
__device__ float2 g_stats[NB];

// fp16 buffers
__device__ __align__(16) __half g_xi16  [2][NB][LL][DI];  // inproj xi half (pre-conv)
__device__ __align__(16) __half g_z16   [2][NB][LL][DI];  // inproj z half
__device__ __align__(16) __half g_xT16  [NB][LL][DM];
__device__ __align__(16) __half g_inw16 [2][2*DI][DM];
__device__ __align__(16) __half g_xch16 [2][NB][LL][DI];
__device__ __align__(16) __half g_xpw16 [2][64][DI];      // xproj W padded 56->64
__device__ __align__(16) __half g_gate16[2][NB][LL][DI];  // written by fused scan
__device__ __align__(16) __half g_outw16[2][DM][DI];
__device__ __align__(16) __half g_ycat16[NB][LL][2*DM];
__device__ __align__(16) __half g_cw16  [2*DM][2*DM];

// ----------------------------- helpers -----------------------------
__device__ __forceinline__ uint32_t smem_to_u32(const void* p) {
    uint32_t a;
    asm("{ .reg .u64 t; cvta.to.shared.u64 t, %1; cvt.u32.u64 %0, t; }" : "=r"(a) : "l"(p));
    return a;
}
__device__ __forceinline__ void ldsm4(uint32_t* r, uint32_t addr){
    asm volatile("ldmatrix.sync.aligned.m8n8.x4.shared.b16 {%0,%1,%2,%3}, [%4];"
        : "=r"(r[0]), "=r"(r[1]), "=r"(r[2]), "=r"(r[3]) : "r"(addr));
}
__device__ __forceinline__ void mma_f16(float* c, const uint32_t* a, const uint32_t* b){
    asm volatile("mma.sync.aligned.m16n8k16.row.col.f32.f16.f16.f32 "
        "{%0,%1,%2,%3}, {%4,%5,%6,%7}, {%8,%9}, {%0,%1,%2,%3};"
        : "+f"(c[0]), "+f"(c[1]), "+f"(c[2]), "+f"(c[3])
        : "r"(a[0]), "r"(a[1]), "r"(a[2]), "r"(a[3]), "r"(b[0]), "r"(b[1]));
}
__device__ __forceinline__ void cpasync16(uint32_t s, const void* g){
    asm volatile("cp.async.cg.shared.global [%0], [%1], 16;" :: "r"(s), "l"(g));
}
#define CP_COMMIT() asm volatile("cp.async.commit_group;" ::: "memory")
template<int N> __device__ __forceinline__ void cpwait(){
    asm volatile("cp.async.wait_group %0;" :: "n"(N) : "memory");
}

// ===========================================================================
// fp16 HMMA GEMM: tile 128x64, K-chunk 64, 4-stage cp.async pipeline.
// mode 0 (inproj): z=dir*2+b; A+=(z&1)*Az; rev=z>>1; W=(z>>1)?W1:W0;
//                  split fp16 output: col<DI -> Ch (xi), else Ch2 (z), stride DI.
// mode 1 (other) : A+z*Az, rev=0, W=z?W1:W0; Ch fp16 out else Cf fp32 (+bias).
// ===========================================================================
#define SMF_W 16384u
#define SMF_STAGE 24576u
#define HMMA16_SMEM (4 * SMF_STAGE)   // 98304

__device__ __forceinline__ void load_chunk16(
    uint32_t bufb, const __half* __restrict__ A, const __half* __restrict__ W,
    int lda, int ldw, int k0, int row0, int col0, int rev, int tid)
{
    #pragma unroll
    for (int i = 0; i < 4; i++) {
        int u = i * 256 + tid;
        int rr = u >> 3, c8 = u & 7;
        int ar = rev ? (LL - 1 - (row0 + rr)) : (row0 + rr);
        uint32_t off = ((uint32_t)(rr * 128 + c8 * 16)) ^ ((uint32_t)(rr & 7) << 4);
        cpasync16(bufb + off, A + (long)ar * lda + k0 + c8 * 8);
    }
    #pragma unroll
    for (int i = 0; i < 2; i++) {
        int u = i * 256 + tid;
        int rr = u >> 3, c8 = u & 7;
        uint32_t off = ((uint32_t)(rr * 128 + c8 * 16)) ^ ((uint32_t)(rr & 7) << 4);
        cpasync16(bufb + SMF_W + off, W + (long)(col0 + rr) * ldw + k0 + c8 * 8);
    }
}

__global__ __launch_bounds__(256, 2) void hmma16(
    const __half* __restrict__ A, int lda, long Az,
    const __half* __restrict__ W0, const __half* __restrict__ W1,
    const float* __restrict__ bias,
    float* __restrict__ Cf, __half* __restrict__ Ch, __half* __restrict__ Ch2,
    int ldc, long Cz, int K, int ncols, int mode)
{
    extern __shared__ __align__(16) char sm[];
    const uint32_t sb = smem_to_u32(sm);

    const int tid  = threadIdx.x;
    const int lane = tid & 31;
    const int warp = tid >> 5;
    const int m0w = (warp >> 1) * 32;
    const int n0w = (warp & 1) * 32;

    const int z = blockIdx.z;
    const int row0 = blockIdx.y * 128;
    const int col0 = blockIdx.x * 64;

    const __half *pA, *pW;
    int rev = 0;
    if (mode == 0) {
        pA = A + (long)(z & 1) * Az;
        rev = z >> 1;
        pW = (z >> 1) ? W1 : W0;
    } else {
        pA = A + (long)z * Az;
        pW = z ? W1 : W0;
    }

    float acc[2][4][4];
    #pragma unroll
    for (int i = 0; i < 2; i++)
        #pragma unroll
        for (int j = 0; j < 4; j++)
            #pragma unroll
            for (int q = 0; q < 4; q++) acc[i][j][q] = 0.f;

    const int lj = lane >> 3;
    const int lr = lane & 7;
    const int nc = K >> 6;

    load_chunk16(sb,             pA, pW, lda, K, 0,  row0, col0, rev, tid); CP_COMMIT();
    load_chunk16(sb + SMF_STAGE, pA, pW, lda, K, 64, row0, col0, rev, tid); CP_COMMIT();

    for (int c = 0; c < nc; c++) {
        if (c + 2 < nc) {
            load_chunk16(sb + ((c + 2) & 3) * SMF_STAGE, pA, pW, lda, K,
                         (c + 2) << 6, row0, col0, rev, tid);
            CP_COMMIT();
            cpwait<2>();
        } else if (c + 1 < nc) {
            cpwait<1>();
        } else {
            cpwait<0>();
        }
        __syncthreads();
        const uint32_t bufb = sb + (c & 3) * SMF_STAGE;
        #pragma unroll
        for (int ks = 0; ks < 4; ks++) {
            const int kb = ks * 16;
            uint32_t af[2][4], bf[2][4];
            #pragma unroll
            for (int mh = 0; mh < 2; mh++) {
                int row = m0w + mh * 16 + ((lj & 1) << 3) + lr;
                int kc  = kb + ((lj >> 1) << 3);
                uint32_t off = ((uint32_t)(row * 128 + kc * 2)) ^ ((uint32_t)(row & 7) << 4);
                ldsm4(af[mh], bufb + off);
            }
            #pragma unroll
            for (int np = 0; np < 2; np++) {
                int row = n0w + np * 16 + ((lj >> 1) << 3) + lr;
                int kc  = kb + ((lj & 1) << 3);
                uint32_t off = ((uint32_t)(row * 128 + kc * 2)) ^ ((uint32_t)(row & 7) << 4);
                ldsm4(bf[np], bufb + SMF_W + off);
            }
            #pragma unroll
            for (int mh = 0; mh < 2; mh++) {
                #pragma unroll
                for (int ng = 0; ng < 4; ng++)
                    mma_f16(acc[mh][ng], af[mh], &bf[ng >> 1][(ng & 1) * 2]);
            }
        }
    }

    // ---- epilogue ----
    const int g = lane >> 2, tig = lane & 3;
    if (mode == 0) {
        __half* Xi = Ch  + (long)z * Cz;
        __half* Zb = Ch2 + (long)z * Cz;
        #pragma unroll
        for (int mh = 0; mh < 2; mh++) {
            #pragma unroll
            for (int ng = 0; ng < 4; ng++) {
                int row = row0 + m0w + mh * 16 + g;
                int col = col0 + n0w + ng * 8 + tig * 2;
                __half* T = (col < DI) ? Xi : Zb;
                int cc = (col < DI) ? col : col - DI;
                *(__half2*)&T[(long)row * DI + cc] =
                    __floats2half2_rn(acc[mh][ng][0], acc[mh][ng][1]);
                *(__half2*)&T[(long)(row + 8) * DI + cc] =
                    __floats2half2_rn(acc[mh][ng][2], acc[mh][ng][3]);
            }
        }
    } else if (Ch) {
        __half* Cb = Ch + (long)z * Cz;
        #pragma unroll
        for (int mh = 0; mh < 2; mh++) {
            #pragma unroll
            for (int ng = 0; ng < 4; ng++) {
                int row = row0 + m0w + mh * 16 + g;
                int col = col0 + n0w + ng * 8 + tig * 2;
                if (col < ncols) {
                    *(__half2*)&Cb[(long)row * ldc + col] =
                        __floats2half2_rn(acc[mh][ng][0], acc[mh][ng][1]);
                    *(__half2*)&Cb[(long)(row + 8) * ldc + col] =
                        __floats2half2_rn(acc[mh][ng][2], acc[mh][ng][3]);
                }
            }
        }
    } else {
        float* Cb = Cf + (long)z * Cz;
        #pragma unroll
        for (int mh = 0; mh < 2; mh++) {
            #pragma unroll
            for (int ng = 0; ng < 4; ng++) {
                int row = row0 + m0w + mh * 16 + g;
                int col = col0 + n0w + ng * 8 + tig * 2;
                if (col < ncols) {
                    float b0 = 0.f, b1 = 0.f;
                    if (bias) { b0 = bias[col]; b1 = bias[col + 1]; }
                    *(float2*)&Cb[(long)row * ldc + col] =
                        make_float2(acc[mh][ng][0] + b0, acc[mh][ng][1] + b1);
                    *(float2*)&Cb[(long)(row + 8) * ldc + col] =
                        make_float2(acc[mh][ng][2] + b0, acc[mh][ng][3] + b1);
                }
            }
        }
    }
}

// ===========================================================================
// fused prep: x transpose + 5 weight converts + xproj pad, single launch.
// ===========================================================================
__global__ __launch_bounds__(256) void prep_kernel(
    const float* __restrict__ x,
    const float* __restrict__ f_in_w, const float* __restrict__ b_in_w,
    const float* __restrict__ f_out_w, const float* __restrict__ b_out_w,
    const float* __restrict__ c_w,
    const float* __restrict__ f_xproj, const float* __restrict__ b_xproj)
{
    const int bid = blockIdx.x;
    const int tid = threadIdx.x;
    if (bid < 3072) {
        __shared__ float s[32][33];
        const int t0 = (bid & 127) * 32;
        const int c0 = ((bid >> 7) % 12) * 32;
        const int b = bid / 1536;
        const int tx = tid & 31;
        const int ty = tid >> 5;
        #pragma unroll
        for (int j = 0; j < 4; j++)
            s[ty + j*8][tx] = x[((long)b * DM + c0 + ty + j*8) * LL + t0 + tx];
        __syncthreads();
        #pragma unroll
        for (int j = 0; j < 4; j++)
            g_xT16[b][t0 + ty + j*8][c0 + tx] = __float2half(s[tx][ty + j*8]);
        return;
    }
    int r = bid - 3072;
    const float* src = nullptr;
    __half* dst = nullptr;
    if (r < 1152)      { src = f_in_w;  dst = &g_inw16[0][0][0]; }
    else if (r < 2304) { src = b_in_w;  dst = &g_inw16[1][0][0]; r -= 1152; }
    else if (r < 2880) { src = f_out_w; dst = &g_outw16[0][0][0]; r -= 2304; }
    else if (r < 3456) { src = b_out_w; dst = &g_outw16[1][0][0]; r -= 2880; }
    else if (r < 4608) { src = c_w;     dst = &g_cw16[0][0];      r -= 3456; }
    else {
        r -= 4608;
        int i = r * 256 + tid;
        int k = i % DI;
        int row = (i / DI) & 63;
        int dir = i / (64 * DI);
        const float* w = dir ? b_xproj : f_xproj;
        float v = (row < XW) ? w[row * DI + k] : 0.f;
        g_xpw16[dir][row][k] = __float2half(v);
        return;
    }
    int i = r * 256 + tid;
    float2 v = *(const float2*)&src[i * 2];
    ((__half2*)dst)[i] = __floats2half2_rn(v.x, v.y);
}

// ----------------------------- f32x2 helpers (delta_gemm) -----------------------------
__device__ __forceinline__ unsigned long long dup2(float x){
    unsigned long long r; asm("mov.b64 %0, {%1, %1};" : "=l"(r) : "f"(x)); return r;
}
__device__ __forceinline__ void ffma2(unsigned long long &d, unsigned long long a, unsigned long long b){
    asm("fma.rn.f32x2 %0, %1, %2, %0;" : "+l"(d) : "l"(a), "l"(b));
}
__device__ __forceinline__ float2 unpk2(unsigned long long v){
    float2 f; asm("mov.b64 {%0, %1}, %2;" : "=f"(f.x), "=f"(f.y) : "l"(v)); return f;
}

// ===========================================================================
// delta GEMM: delta = softplus(dt @ dtw^T + dtb)
// ===========================================================================
__global__ __launch_bounds__(256) void delta_gemm(
    const float* __restrict__ dtw0, const float* __restrict__ dtb0,
    const float* __restrict__ dtw1, const float* __restrict__ dtb1)
{
    __shared__ float As[DR][64];
    __shared__ float Bs[DR][64];
    const int dir = blockIdx.z;
    const float* Ab  = &g_xdbl[dir][0][0][0];
    float* pdl = &g_delta[dir][0][0][0];
    const float* dtw = dir ? dtw1 : dtw0;
    const float* dtb = dir ? dtb1 : dtb0;
    const int row0 = blockIdx.y * 64;
    const int col0 = blockIdx.x * 64;
    const int tid = threadIdx.x;
    const int tx = tid & 15, ty = tid >> 4;

    for (int i = tid; i < 64 * DR; i += 256) {
        int r = i / DR, k = i % DR;
        As[k][r] = Ab[(long)(row0 + r) * XW + k];
        Bs[k][r] = dtw[(long)(col0 + r) * DR + k];
    }
    __syncthreads();

    unsigned long long acc[2][4];
    #pragma unroll
    for (int i = 0; i < 2; i++)
        #pragma unroll
        for (int j = 0; j < 4; j++) acc[i][j] = 0ull;

    #pragma unroll
    for (int k = 0; k < DR; k++) {
        unsigned long long a01 = *(const unsigned long long*)&As[k][ty*4];
        unsigned long long a23 = *(const unsigned long long*)&As[k][ty*4+2];
        float4 bv = *(const float4*)&Bs[k][tx*4];
        unsigned long long b0 = dup2(bv.x), b1 = dup2(bv.y), b2 = dup2(bv.z), b3 = dup2(bv.w);
        ffma2(acc[0][0], a01, b0); ffma2(acc[0][1], a01, b1);
        ffma2(acc[0][2], a01, b2); ffma2(acc[0][3], a01, b3);
        ffma2(acc[1][0], a23, b0); ffma2(acc[1][1], a23, b1);
        ffma2(acc[1][2], a23, b2); ffma2(acc[1][3], a23, b3);
    }
    const int colb = col0 + tx*4;
    float4 bias4 = *(const float4*)&dtb[colb];
    float bsv[4] = {bias4.x, bias4.y, bias4.z, bias4.w};
    float out[4][4];
    #pragma unroll
    for (int i = 0; i < 2; i++)
        #pragma unroll
        for (int j = 0; j < 4; j++) {
            float2 f = unpk2(acc[i][j]);
            out[2*i][j] = f.x; out[2*i+1][j] = f.y;
        }
    #pragma unroll
    for (int r = 0; r < 4; r++) {
        long row = row0 + ty*4 + r;
        float dl[4];
        #pragma unroll
        for (int j = 0; j < 4; j++) {
            float s = out[r][j] + bsv[j];
            dl[j] = fmaxf(s, 0.f) + log1pf(__expf(-fabsf(s)));
        }
        *(float4*)&pdl[row * DI + colb] = make_float4(dl[0], dl[1], dl[2], dl[3]);
    }
}

// ----------------------------- B/C repack -----------------------------
__global__ __launch_bounds__(256) void repack_kernel()
{
    int id = blockIdx.x * 256 + threadIdx.x;
    if (id >= 2 * NB * LL * 2 * DS) return;
    int n = id & 15;
    int which = (id >> 4) & 1;
    int t = (id >> 5) & (LL - 1);
    int b = (id >> 17) & 1;
    int dir = (id >> 18) & 1;
    float v = g_xdbl[dir][b][t][DR + which * DS + n];
    float* dst = which ? &g_Cc[dir][b][0][0][0] : &g_Bc[dir][b][0][0][0];
    dst[(t >> 2) * (DS*4) + n * 4 + (t & 3)] = v;
}

// ----------------------------- conv+silu: 2 channels x 4 t per thread, fp16 in -----------------------------
__global__ __launch_bounds__(256) void conv_silu_kernel(
    const float* __restrict__ cw0, const float* __restrict__ cb0,
    const float* __restrict__ cw1, const float* __restrict__ cb1)
{
    long id = (long)blockIdx.x * 256 + threadIdx.x;
    const long total = (long)2 * NB * (LL/4) * (DI/2);
    if (id >= total) return;
    int dp = (int)(id % (DI/2)); long r = id / (DI/2);
    int t4 = (int)(r % (LL/4)); r /= (LL/4);
    int b = (int)(r % NB); int dir = (int)(r / NB);
    const float* cw = dir ? cw1 : cw0;
    const float* cb = dir ? cb1 : cb0;
    const int d = dp * 2;
    const __half* xi = &g_xi16[dir][b][0][d];
    const int tb = t4 * 4;
    float2 rv[7];
    #pragma unroll
    for (int i = 0; i < 7; i++) {
        int tt = tb - 3 + i;
        rv[i] = (tt >= 0) ? __half22float2(*(const __half2*)&xi[(long)tt * DI])
                          : make_float2(0.f, 0.f);
    }
    float4 w0 = *(const float4*)&cw[d * 4];
    float4 w1 = *(const float4*)&cw[d * 4 + 4];
    float cb0v = cb[d], cb1v = cb[d + 1];
    #pragma unroll
    for (int j = 0; j < 4; j++) {
        float a0 = cb0v + w0.x*rv[j].x + w0.y*rv[j+1].x + w0.z*rv[j+2].x + w0.w*rv[j+3].x;
        float a1 = cb1v + w1.x*rv[j].y + w1.y*rv[j+1].y + w1.z*rv[j+2].y + w1.w*rv[j+3].y;
        float v0 = a0 / (1.f + __expf(-a0));
        float v1 = a1 / (1.f + __expf(-a1));
        *(float2*)&g_xc[dir][b][tb + j][d] = make_float2(v0, v1);
        *(__half2*)&g_xch16[dir][b][tb + j][d] = __floats2half2_rn(v0, v1);
    }
}

// ===========================================================================
// selective scan + fused gate. Block = 128 threads = 8 d x 16 n; 384 blocks.
// dA computed via integer powers of e1=exp(dl*A0) (one MUFU per (d,t), staged),
// with per-thread verified fallback to __expf for non-integer-ratio A.
// ===========================================================================
#define SCAN_T 64
__global__ __launch_bounds__(128) void scan_kernel(
    const float* __restrict__ Al0, const float* __restrict__ Al1,
    const float* __restrict__ D0,  const float* __restrict__ D1)
{
    __shared__ float s_dl[SCAN_T][8];
    __shared__ float s_xc[SCAN_T][8];
    __shared__ float s_z [SCAN_T][8];
    __shared__ float s_e1[SCAN_T][8];
    __shared__ float s_a0[8];
    __shared__ __half s_g[SCAN_T][8];

    const int bx = blockIdx.x;          // 0..383
    const int dgrp = bx % 96;
    const int b = (bx / 96) & 1;
    const int dir = bx / 192;
    const int d0 = dgrp * 8;
    const int tid = threadIdx.x;
    const int n = tid & 15;
    const int dloc = tid >> 4;          // 0..7
    const int d = d0 + dloc;

    const float* Al  = dir ? Al1 : Al0;
    const float* Dpt = dir ? D1 : D0;
    const float Acoef = -__expf(Al[d*DS + n]);
    const float Dv = Dpt[d];

    // fast-path detection: Acoef_n == k * Acoef_0 (integer k in [1,16])
    const float A0 = -__expf(Al[d*DS]);
    const float ratio = Acoef / A0;
    const int kpow = __float2int_rn(ratio);
    const bool fast = (fabsf(ratio - (float)kpow) < 1e-3f * fabsf(ratio))
                      && kpow >= 1 && kpow <= 16;

    if (tid < 8) s_a0[tid] = -__expf(Al[(d0 + tid) * DS]);

    const float* pdl = &g_delta[dir][b][0][0];
    const float* pxc = &g_xc[dir][b][0][0];
    const __half* pz = &g_z16[dir][b][0][0];
    const float4* pB = (const float4*)&g_Bc[dir][b][0][0][0];
    const float4* pC = (const float4*)&g_Cc[dir][b][0][0][0];
    __half* pg = &g_gate16[dir][b][0][0];

    const int l_tl = tid >> 1;          // 0..63
    const int l_c4 = (tid & 1) * 4;     // 0 or 4

    float h = 0.f;
    for (int t0 = 0; t0 < LL; t0 += SCAN_T) {
        __syncthreads();
        {
            long rbase = (long)(t0 + l_tl) * DI + d0 + l_c4;
            float4 vdl = *(const float4*)&pdl[rbase];
            float4 vxc = *(const float4*)&pxc[rbase];
            uint2 vzr = *(const uint2*)&pz[rbase];
            __half2 z01 = *(__half2*)&vzr.x;
            __half2 z23 = *(__half2*)&vzr.y;
            float2 f01 = __half22float2(z01);
            float2 f23 = __half22float2(z23);
            *(float4*)&s_dl[l_tl][l_c4] = vdl;
            *(float4*)&s_xc[l_tl][l_c4] = vxc;
            *(float4*)&s_z [l_tl][l_c4] = make_float4(f01.x, f01.y, f23.x, f23.y);
            float4 ve;
            ve.x = __expf(vdl.x * s_a0[l_c4 + 0]);
            ve.y = __expf(vdl.y * s_a0[l_c4 + 1]);
            ve.z = __expf(vdl.z * s_a0[l_c4 + 2]);
            ve.w = __expf(vdl.w * s_a0[l_c4 + 3]);
            *(float4*)&s_e1[l_tl][l_c4] = ve;
        }
        __syncthreads();
        #pragma unroll 2
        for (int t4 = 0; t4 < SCAN_T/4; t4++) {
            int tt4 = (t0 >> 2) + t4;
            float4 Bv = __ldg(&pB[tt4*16 + n]);
            float4 Cv = __ldg(&pC[tt4*16 + n]);
            float p[4];
            #pragma unroll
            for (int j = 0; j < 4; j++) {
                int tl = t4*4 + j;
                float dl  = s_dl[tl][dloc];
                float xcv = s_xc[tl][dloc];
                float uu = dl * xcv;
                float dA;
                if (fast) {
                    float e1 = s_e1[tl][dloc];
                    float p2 = e1 * e1;
                    float p4 = p2 * p2;
                    float p8 = p4 * p4;
                    dA = 1.f;
                    if (kpow & 1)  dA *= e1;
                    if (kpow & 2)  dA *= p2;
                    if (kpow & 4)  dA *= p4;
                    if (kpow & 8)  dA *= p8;
                    if (kpow & 16) dA *= p8 * p8;
                } else {
                    dA = __expf(dl * Acoef);
                }
                float Bj = (j==0)?Bv.x:(j==1)?Bv.y:(j==2)?Bv.z:Bv.w;
                float Cj = (j==0)?Cv.x:(j==1)?Cv.y:(j==2)?Cv.z:Cv.w;
                h = fmaf(dA, h, uu * Bj);
                p[j] = h * Cj;
            }
            #pragma unroll
            for (int s = 1; s < 16; s <<= 1) {
                p[0] += __shfl_xor_sync(0xffffffffu, p[0], s);
                p[1] += __shfl_xor_sync(0xffffffffu, p[1], s);
                p[2] += __shfl_xor_sync(0xffffffffu, p[2], s);
                p[3] += __shfl_xor_sync(0xffffffffu, p[3], s);
            }
            if (n == 0) {
                #pragma unroll
                for (int j = 0; j < 4; j++) {
                    int tl = t4*4 + j;
                    float zv = s_z[tl][dloc];
                    float yv = p[j] + s_xc[tl][dloc] * Dv;
                    float gv = yv * (zv / (1.f + __expf(-zv)));
                    s_g[tl][dloc] = __float2half(gv);
                }
            }
        }
        __syncthreads();
        #pragma unroll
        for (int q = 0; q < 2; q++) {
            int u = tid + q * 128;          // 0..255 -> 64 rows x 4 half2
            int row = u >> 2, cp = u & 3;
            __half2 v = *(__half2*)&s_g[row][cp*2];
            *(__half2*)&pg[(long)(t0 + row) * DI + d0 + cp*2] = v;
        }
    }
}

// ----------------------------- GLU + partial stats -----------------------------
__global__ __launch_bounds__(256) void glu_kernel()
{
    const int batch = blockIdx.y;
    const int tid = threadIdx.x;
    float lsum = 0.f, lssq = 0.f;
    const float* yc = &g_yc[batch][0][0];
    float* gl = &g_glu[batch][0][0];
    for (int it = 0; it < 128; it++) {
        long e = (long)blockIdx.x * 32768 + (long)it * 256 + tid;
        int t = (int)(e / DM), o = (int)(e % DM);
        float a  = yc[(long)t * (2*DM) + o];
        float bg = yc[(long)t * (2*DM) + DM + o];
        float g = a * (1.f / (1.f + __expf(-bg)));
        gl[e] = g;
        lsum += g; lssq += g * g;
    }
    __shared__ float s1[256], s2[256];
    s1[tid] = lsum; s2[tid] = lssq;
    __syncthreads();
    for (int s = 128; s > 0; s >>= 1) {
        if (tid < s) { s1[tid] += s1[tid+s]; s2[tid] += s2[tid+s]; }
        __syncthreads();
    }
    if (tid == 0) g_part[batch][blockIdx.x] = make_float2(s1[0], s2[0]);
}

__global__ void stats_kernel()
{
    int b = threadIdx.x;
    if (b < NB) {
        float sum = 0.f, ssq = 0.f;
        for (int i = 0; i < 48; i++) { float2 p = g_part[b][i]; sum += p.x; ssq += p.y; }
        const float inv = 1.f / ((float)DM * (float)LL);
        float mu = sum * inv;
        float var = ssq * inv - mu * mu;
        g_stats[b] = make_float2(mu, rsqrtf(var + 1e-5f));
    }
}

// ----------------------------- normalize + transpose to output [b][c][t] -----------------------------
__global__ __launch_bounds__(256) void norm_kernel(
    const float* __restrict__ gnw, const float* __restrict__ gnb,
    float* __restrict__ out)
{
    __shared__ float s[32][33];
    const int b = blockIdx.z;
    const int t0 = blockIdx.x * 32;
    const int c0 = blockIdx.y * 32;
    const int tx = threadIdx.x & 31;
    const int ty = threadIdx.x >> 5;
    #pragma unroll
    for (int j = 0; j < 4; j++) {
        int t = t0 + ty + j*8;
        s[ty + j*8][tx] = g_glu[b][t][c0 + tx];
    }
    __syncthreads();
    float2 st = g_stats[b];
    #pragma unroll
    for (int j = 0; j < 4; j++) {
        int c = c0 + ty + j*8;
        float v = s[tx][ty + j*8];
        out[((long)b * DM + c) * LL + t0 + tx] = (v - st.x) * st.y * gnw[c] + gnb[c];
    }
}

// ----------------------------- launch -----------------------------
extern "C" void kernel_launch(void* const* d_in, const int* in_sizes, int n_in,
                              void* d_out, int out_size)
{
    (void)in_sizes; (void)n_in; (void)out_size;
    const float* x        = (const float*)d_in[0];
    const float* f_in_w   = (const float*)d_in[1];
    const float* f_conv_w = (const float*)d_in[2];
    const float* f_conv_b = (const float*)d_in[3];
    const float* f_xproj  = (const float*)d_in[4];
    const float* f_dt_w   = (const float*)d_in[5];
    const float* f_dt_b   = (const float*)d_in[6];
    const float* f_A_log  = (const float*)d_in[7];
    const float* f_D      = (const float*)d_in[8];
    const float* f_out_w  = (const float*)d_in[9];
    const float* b_in_w   = (const float*)d_in[10];
    const float* b_conv_w = (const float*)d_in[11];
    const float* b_conv_b = (const float*)d_in[12];
    const float* b_xproj  = (const float*)d_in[13];
    const float* b_dt_w   = (const float*)d_in[14];
    const float* b_dt_b   = (const float*)d_in[15];
    const float* b_A_log  = (const float*)d_in[16];
    const float* b_D      = (const float*)d_in[17];
    const float* b_out_w  = (const float*)d_in[18];
    const float* c_w      = (const float*)d_in[19];
    const float* c_b      = (const float*)d_in[20];
    const float* gn_w     = (const float*)d_in[21];
    const float* gn_b     = (const float*)d_in[22];
    float* out = (float*)d_out;

    float *pxdbl, *pyc;
    cudaGetSymbolAddress((void**)&pxdbl, g_xdbl);
    cudaGetSymbolAddress((void**)&pyc,   g_yc);
    __half *pxT16, *pinw16, *pxi16, *pz16, *pxch16, *pxpw16, *pgate16, *poutw16, *pycat16, *pcw16;
    cudaGetSymbolAddress((void**)&pxT16,   g_xT16);
    cudaGetSymbolAddress((void**)&pinw16,  g_inw16);
    cudaGetSymbolAddress((void**)&pxi16,   g_xi16);
    cudaGetSymbolAddress((void**)&pz16,    g_z16);
    cudaGetSymbolAddress((void**)&pxch16,  g_xch16);
    cudaGetSymbolAddress((void**)&pxpw16,  g_xpw16);
    cudaGetSymbolAddress((void**)&pgate16, g_gate16);
    cudaGetSymbolAddress((void**)&poutw16, g_outw16);
    cudaGetSymbolAddress((void**)&pycat16, g_ycat16);
    cudaGetSymbolAddress((void**)&pcw16,   g_cw16);

    static bool attr_set = false;
    if (!attr_set) {
        cudaFuncSetAttribute(hmma16, cudaFuncAttributeMaxDynamicSharedMemorySize, HMMA16_SMEM);
        attr_set = true;
    }

    const long INW  = (long)(2*DI) * DM;
    const long OUTW = (long)DM * DI;

    // 0) fused prep
    prep_kernel<<<8064, 256>>>(x, f_in_w, b_in_w, f_out_w, b_out_w, c_w, f_xproj, b_xproj);

    // 1) in-projection: z=dir*2+b, M=4096, N=1536, K=384 -> fp16 xi/z split
    hmma16<<<dim3(24, 32, 4), 256, HMMA16_SMEM>>>(
        pxT16, DM, (long)LL*DM,
        pinw16, pinw16 + INW, nullptr,
        nullptr, pxi16, pz16, DI, (long)LL*DI, DM, 2*DI, 0);

    // 2) depthwise causal conv + silu
    {
        long total = (long)2 * NB * (LL/4) * (DI/2);
        conv_silu_kernel<<<(unsigned)((total + 255) / 256), 256>>>(f_conv_w, f_conv_b, b_conv_w, b_conv_b);
    }

    // 3) x-projection: z=dir, M=8192, N=64(pad), K=768 -> fp32 g_xdbl
    hmma16<<<dim3(1, 64, 2), 256, HMMA16_SMEM>>>(
        pxch16, DI, (long)NB*LL*DI,
        pxpw16, pxpw16 + 64*DI, nullptr,
        pxdbl, nullptr, nullptr, XW, (long)NB*LL*XW, DI, XW, 1);

    // 4) delta; 4b) repack; 5) fused scan+gate (power-trick dA)
    delta_gemm<<<dim3(DI/64, (NB*LL)/64, 2), 256>>>(f_dt_w, f_dt_b, b_dt_w, b_dt_b);
    repack_kernel<<<2048, 256>>>();
    scan_kernel<<<384, 128>>>(f_A_log, b_A_log, f_D, b_D);

    // 6) out-projection: z=dir, M=8192, N=384, K=768 -> fp16 ycat col halves
    hmma16<<<dim3(6, 64, 2), 256, HMMA16_SMEM>>>(
        pgate16, DI, (long)NB*LL*DI,
        poutw16, poutw16 + OUTW, nullptr,
        nullptr, pycat16, nullptr, 2*DM, (long)DM, DI, DM, 1);

    // 7) final 1x1 conv: M=8192, N=768, K=768, bias -> fp32 g_yc
    hmma16<<<dim3(12, 64, 1), 256, HMMA16_SMEM>>>(
        pycat16, 2*DM, 0L,
        pcw16, pcw16, c_b,
        pyc, nullptr, nullptr, 2*DM, 0L, 2*DM, 2*DM, 1);

    // 8) GLU + stats + normalize
    glu_kernel<<<dim3(48, 2), 256>>>();
    stats_kernel<<<1, 32>>>();
    norm_kernel<<<dim3(LL/32, DM/32, NB), 256>>>(gn_w, gn_b, out);
}

// round 16
// speedup vs baseline: 1.1642x; 1.1642x over previous
#include <cuda_runtime.h>
#include <cuda_fp16.h>
#include <cstdint>

#define LL 4096
#define DM 384
#define DI 768
#define DS 16
#define DR 24
#define NB 2
#define XW (DR + 2*DS)   // 56

// ----------------------------- scratch (device globals) -----------------------------
__device__ float g_xdbl [2][NB][LL][XW];     // x-proj output (dt | B | C)
__device__ float g_delta[2][NB][LL][DI];     // softplus(dt@dtw+b)
__device__ float g_Bc   [2][NB][LL/4][DS][4];
__device__ float g_Cc   [2][NB][LL/4][DS][4];
__device__ float g_yc   [NB][LL][2*DM];
__device__ float g_glu  [NB][LL][DM];
__device__ float2 g_part[NB][64];
__device__ float2 g_stats[NB];

// fp16 buffers
__device__ __align__(16) __half g_xi16  [2][NB][LL][DI];  // inproj xi half (pre-conv)
__device__ __align__(16) __half g_z16   [2][NB][LL][DI];  // inproj z half
__device__ __align__(16) __half g_xT16  [NB][LL][DM];
__device__ __align__(16) __half g_inw16 [2][2*DI][DM];
__device__ __align__(16) __half g_xch16 [2][NB][LL][DI];  // conv+silu output (sole copy)
__device__ __align__(16) __half g_xpw16 [2][64][DI];      // xproj W padded 56->64
__device__ __align__(16) __half g_gate16[2][NB][LL][DI];  // written by fused scan
__device__ __align__(16) __half g_outw16[2][DM][DI];
__device__ __align__(16) __half g_ycat16[NB][LL][2*DM];
__device__ __align__(16) __half g_cw16  [2*DM][2*DM];

// ----------------------------- helpers -----------------------------
__device__ __forceinline__ uint32_t smem_to_u32(const void* p) {
    uint32_t a;
    asm("{ .reg .u64 t; cvta.to.shared.u64 t, %1; cvt.u32.u64 %0, t; }" : "=r"(a) : "l"(p));
    return a;
}
__device__ __forceinline__ void ldsm4(uint32_t* r, uint32_t addr){
    asm volatile("ldmatrix.sync.aligned.m8n8.x4.shared.b16 {%0,%1,%2,%3}, [%4];"
        : "=r"(r[0]), "=r"(r[1]), "=r"(r[2]), "=r"(r[3]) : "r"(addr));
}
__device__ __forceinline__ void mma_f16(float* c, const uint32_t* a, const uint32_t* b){
    asm volatile("mma.sync.aligned.m16n8k16.row.col.f32.f16.f16.f32 "
        "{%0,%1,%2,%3}, {%4,%5,%6,%7}, {%8,%9}, {%0,%1,%2,%3};"
        : "+f"(c[0]), "+f"(c[1]), "+f"(c[2]), "+f"(c[3])
        : "r"(a[0]), "r"(a[1]), "r"(a[2]), "r"(a[3]), "r"(b[0]), "r"(b[1]));
}
__device__ __forceinline__ void cpasync16(uint32_t s, const void* g){
    asm volatile("cp.async.cg.shared.global [%0], [%1], 16;" :: "r"(s), "l"(g));
}
#define CP_COMMIT() asm volatile("cp.async.commit_group;" ::: "memory")
template<int N> __device__ __forceinline__ void cpwait(){
    asm volatile("cp.async.wait_group %0;" :: "n"(N) : "memory");
}

// ===========================================================================
// fp16 HMMA GEMM: tile 128x64, K-chunk 64, 4-stage cp.async pipeline.
// mode 0 (inproj): z=dir*2+b; A+=(z&1)*Az; rev=z>>1; W=(z>>1)?W1:W0;
//                  split fp16 output: col<DI -> Ch (xi), else Ch2 (z), stride DI.
// mode 1 (other) : A+z*Az, rev=0, W=z?W1:W0; Ch fp16 out else Cf fp32 (+bias).
// ===========================================================================
#define SMF_W 16384u
#define SMF_STAGE 24576u
#define HMMA16_SMEM (4 * SMF_STAGE)   // 98304

__device__ __forceinline__ void load_chunk16(
    uint32_t bufb, const __half* __restrict__ A, const __half* __restrict__ W,
    int lda, int ldw, int k0, int row0, int col0, int rev, int tid)
{
    #pragma unroll
    for (int i = 0; i < 4; i++) {
        int u = i * 256 + tid;
        int rr = u >> 3, c8 = u & 7;
        int ar = rev ? (LL - 1 - (row0 + rr)) : (row0 + rr);
        uint32_t off = ((uint32_t)(rr * 128 + c8 * 16)) ^ ((uint32_t)(rr & 7) << 4);
        cpasync16(bufb + off, A + (long)ar * lda + k0 + c8 * 8);
    }
    #pragma unroll
    for (int i = 0; i < 2; i++) {
        int u = i * 256 + tid;
        int rr = u >> 3, c8 = u & 7;
        uint32_t off = ((uint32_t)(rr * 128 + c8 * 16)) ^ ((uint32_t)(rr & 7) << 4);
        cpasync16(bufb + SMF_W + off, W + (long)(col0 + rr) * ldw + k0 + c8 * 8);
    }
}

__global__ __launch_bounds__(256, 2) void hmma16(
    const __half* __restrict__ A, int lda, long Az,
    const __half* __restrict__ W0, const __half* __restrict__ W1,
    const float* __restrict__ bias,
    float* __restrict__ Cf, __half* __restrict__ Ch, __half* __restrict__ Ch2,
    int ldc, long Cz, int K, int ncols, int mode)
{
    extern __shared__ __align__(16) char sm[];
    const uint32_t sb = smem_to_u32(sm);

    const int tid  = threadIdx.x;
    const int lane = tid & 31;
    const int warp = tid >> 5;
    const int m0w = (warp >> 1) * 32;
    const int n0w = (warp & 1) * 32;

    const int z = blockIdx.z;
    const int row0 = blockIdx.y * 128;
    const int col0 = blockIdx.x * 64;

    const __half *pA, *pW;
    int rev = 0;
    if (mode == 0) {
        pA = A + (long)(z & 1) * Az;
        rev = z >> 1;
        pW = (z >> 1) ? W1 : W0;
    } else {
        pA = A + (long)z * Az;
        pW = z ? W1 : W0;
    }

    float acc[2][4][4];
    #pragma unroll
    for (int i = 0; i < 2; i++)
        #pragma unroll
        for (int j = 0; j < 4; j++)
            #pragma unroll
            for (int q = 0; q < 4; q++) acc[i][j][q] = 0.f;

    const int lj = lane >> 3;
    const int lr = lane & 7;
    const int nc = K >> 6;

    load_chunk16(sb,             pA, pW, lda, K, 0,  row0, col0, rev, tid); CP_COMMIT();
    load_chunk16(sb + SMF_STAGE, pA, pW, lda, K, 64, row0, col0, rev, tid); CP_COMMIT();

    for (int c = 0; c < nc; c++) {
        if (c + 2 < nc) {
            load_chunk16(sb + ((c + 2) & 3) * SMF_STAGE, pA, pW, lda, K,
                         (c + 2) << 6, row0, col0, rev, tid);
            CP_COMMIT();
            cpwait<2>();
        } else if (c + 1 < nc) {
            cpwait<1>();
        } else {
            cpwait<0>();
        }
        __syncthreads();
        const uint32_t bufb = sb + (c & 3) * SMF_STAGE;
        #pragma unroll
        for (int ks = 0; ks < 4; ks++) {
            const int kb = ks * 16;
            uint32_t af[2][4], bf[2][4];
            #pragma unroll
            for (int mh = 0; mh < 2; mh++) {
                int row = m0w + mh * 16 + ((lj & 1) << 3) + lr;
                int kc  = kb + ((lj >> 1) << 3);
                uint32_t off = ((uint32_t)(row * 128 + kc * 2)) ^ ((uint32_t)(row & 7) << 4);
                ldsm4(af[mh], bufb + off);
            }
            #pragma unroll
            for (int np = 0; np < 2; np++) {
                int row = n0w + np * 16 + ((lj >> 1) << 3) + lr;
                int kc  = kb + ((lj & 1) << 3);
                uint32_t off = ((uint32_t)(row * 128 + kc * 2)) ^ ((uint32_t)(row & 7) << 4);
                ldsm4(bf[np], bufb + SMF_W + off);
            }
            #pragma unroll
            for (int mh = 0; mh < 2; mh++) {
                #pragma unroll
                for (int ng = 0; ng < 4; ng++)
                    mma_f16(acc[mh][ng], af[mh], &bf[ng >> 1][(ng & 1) * 2]);
            }
        }
    }

    // ---- epilogue ----
    const int g = lane >> 2, tig = lane & 3;
    if (mode == 0) {
        __half* Xi = Ch  + (long)z * Cz;
        __half* Zb = Ch2 + (long)z * Cz;
        #pragma unroll
        for (int mh = 0; mh < 2; mh++) {
            #pragma unroll
            for (int ng = 0; ng < 4; ng++) {
                int row = row0 + m0w + mh * 16 + g;
                int col = col0 + n0w + ng * 8 + tig * 2;
                __half* T = (col < DI) ? Xi : Zb;
                int cc = (col < DI) ? col : col - DI;
                *(__half2*)&T[(long)row * DI + cc] =
                    __floats2half2_rn(acc[mh][ng][0], acc[mh][ng][1]);
                *(__half2*)&T[(long)(row + 8) * DI + cc] =
                    __floats2half2_rn(acc[mh][ng][2], acc[mh][ng][3]);
            }
        }
    } else if (Ch) {
        __half* Cb = Ch + (long)z * Cz;
        #pragma unroll
        for (int mh = 0; mh < 2; mh++) {
            #pragma unroll
            for (int ng = 0; ng < 4; ng++) {
                int row = row0 + m0w + mh * 16 + g;
                int col = col0 + n0w + ng * 8 + tig * 2;
                if (col < ncols) {
                    *(__half2*)&Cb[(long)row * ldc + col] =
                        __floats2half2_rn(acc[mh][ng][0], acc[mh][ng][1]);
                    *(__half2*)&Cb[(long)(row + 8) * ldc + col] =
                        __floats2half2_rn(acc[mh][ng][2], acc[mh][ng][3]);
                }
            }
        }
    } else {
        float* Cb = Cf + (long)z * Cz;
        #pragma unroll
        for (int mh = 0; mh < 2; mh++) {
            #pragma unroll
            for (int ng = 0; ng < 4; ng++) {
                int row = row0 + m0w + mh * 16 + g;
                int col = col0 + n0w + ng * 8 + tig * 2;
                if (col < ncols) {
                    float b0 = 0.f, b1 = 0.f;
                    if (bias) { b0 = bias[col]; b1 = bias[col + 1]; }
                    *(float2*)&Cb[(long)row * ldc + col] =
                        make_float2(acc[mh][ng][0] + b0, acc[mh][ng][1] + b1);
                    *(float2*)&Cb[(long)(row + 8) * ldc + col] =
                        make_float2(acc[mh][ng][2] + b0, acc[mh][ng][3] + b1);
                }
            }
        }
    }
}

// ===========================================================================
// fused prep: x transpose + 5 weight converts + xproj pad, single launch.
// ===========================================================================
__global__ __launch_bounds__(256) void prep_kernel(
    const float* __restrict__ x,
    const float* __restrict__ f_in_w, const float* __restrict__ b_in_w,
    const float* __restrict__ f_out_w, const float* __restrict__ b_out_w,
    const float* __restrict__ c_w,
    const float* __restrict__ f_xproj, const float* __restrict__ b_xproj)
{
    const int bid = blockIdx.x;
    const int tid = threadIdx.x;
    if (bid < 3072) {
        __shared__ float s[32][33];
        const int t0 = (bid & 127) * 32;
        const int c0 = ((bid >> 7) % 12) * 32;
        const int b = bid / 1536;
        const int tx = tid & 31;
        const int ty = tid >> 5;
        #pragma unroll
        for (int j = 0; j < 4; j++)
            s[ty + j*8][tx] = x[((long)b * DM + c0 + ty + j*8) * LL + t0 + tx];
        __syncthreads();
        #pragma unroll
        for (int j = 0; j < 4; j++)
            g_xT16[b][t0 + ty + j*8][c0 + tx] = __float2half(s[tx][ty + j*8]);
        return;
    }
    int r = bid - 3072;
    const float* src = nullptr;
    __half* dst = nullptr;
    if (r < 1152)      { src = f_in_w;  dst = &g_inw16[0][0][0]; }
    else if (r < 2304) { src = b_in_w;  dst = &g_inw16[1][0][0]; r -= 1152; }
    else if (r < 2880) { src = f_out_w; dst = &g_outw16[0][0][0]; r -= 2304; }
    else if (r < 3456) { src = b_out_w; dst = &g_outw16[1][0][0]; r -= 2880; }
    else if (r < 4608) { src = c_w;     dst = &g_cw16[0][0];      r -= 3456; }
    else {
        r -= 4608;
        int i = r * 256 + tid;
        int k = i % DI;
        int row = (i / DI) & 63;
        int dir = i / (64 * DI);
        const float* w = dir ? b_xproj : f_xproj;
        float v = (row < XW) ? w[row * DI + k] : 0.f;
        g_xpw16[dir][row][k] = __float2half(v);
        return;
    }
    int i = r * 256 + tid;
    float2 v = *(const float2*)&src[i * 2];
    ((__half2*)dst)[i] = __floats2half2_rn(v.x, v.y);
}

// ----------------------------- f32x2 helpers (delta_gemm) -----------------------------
__device__ __forceinline__ unsigned long long dup2(float x){
    unsigned long long r; asm("mov.b64 %0, {%1, %1};" : "=l"(r) : "f"(x)); return r;
}
__device__ __forceinline__ void ffma2(unsigned long long &d, unsigned long long a, unsigned long long b){
    asm("fma.rn.f32x2 %0, %1, %2, %0;" : "+l"(d) : "l"(a), "l"(b));
}
__device__ __forceinline__ float2 unpk2(unsigned long long v){
    float2 f; asm("mov.b64 {%0, %1}, %2;" : "=f"(f.x), "=f"(f.y) : "l"(v)); return f;
}

// ===========================================================================
// delta GEMM: delta = softplus(dt @ dtw^T + dtb)
// ===========================================================================
__global__ __launch_bounds__(256) void delta_gemm(
    const float* __restrict__ dtw0, const float* __restrict__ dtb0,
    const float* __restrict__ dtw1, const float* __restrict__ dtb1)
{
    __shared__ float As[DR][64];
    __shared__ float Bs[DR][64];
    const int dir = blockIdx.z;
    const float* Ab  = &g_xdbl[dir][0][0][0];
    float* pdl = &g_delta[dir][0][0][0];
    const float* dtw = dir ? dtw1 : dtw0;
    const float* dtb = dir ? dtb1 : dtb0;
    const int row0 = blockIdx.y * 64;
    const int col0 = blockIdx.x * 64;
    const int tid = threadIdx.x;
    const int tx = tid & 15, ty = tid >> 4;

    for (int i = tid; i < 64 * DR; i += 256) {
        int r = i / DR, k = i % DR;
        As[k][r] = Ab[(long)(row0 + r) * XW + k];
        Bs[k][r] = dtw[(long)(col0 + r) * DR + k];
    }
    __syncthreads();

    unsigned long long acc[2][4];
    #pragma unroll
    for (int i = 0; i < 2; i++)
        #pragma unroll
        for (int j = 0; j < 4; j++) acc[i][j] = 0ull;

    #pragma unroll
    for (int k = 0; k < DR; k++) {
        unsigned long long a01 = *(const unsigned long long*)&As[k][ty*4];
        unsigned long long a23 = *(const unsigned long long*)&As[k][ty*4+2];
        float4 bv = *(const float4*)&Bs[k][tx*4];
        unsigned long long b0 = dup2(bv.x), b1 = dup2(bv.y), b2 = dup2(bv.z), b3 = dup2(bv.w);
        ffma2(acc[0][0], a01, b0); ffma2(acc[0][1], a01, b1);
        ffma2(acc[0][2], a01, b2); ffma2(acc[0][3], a01, b3);
        ffma2(acc[1][0], a23, b0); ffma2(acc[1][1], a23, b1);
        ffma2(acc[1][2], a23, b2); ffma2(acc[1][3], a23, b3);
    }
    const int colb = col0 + tx*4;
    float4 bias4 = *(const float4*)&dtb[colb];
    float bsv[4] = {bias4.x, bias4.y, bias4.z, bias4.w};
    float out[4][4];
    #pragma unroll
    for (int i = 0; i < 2; i++)
        #pragma unroll
        for (int j = 0; j < 4; j++) {
            float2 f = unpk2(acc[i][j]);
            out[2*i][j] = f.x; out[2*i+1][j] = f.y;
        }
    #pragma unroll
    for (int r = 0; r < 4; r++) {
        long row = row0 + ty*4 + r;
        float dl[4];
        #pragma unroll
        for (int j = 0; j < 4; j++) {
            float s = out[r][j] + bsv[j];
            dl[j] = fmaxf(s, 0.f) + log1pf(__expf(-fabsf(s)));
        }
        *(float4*)&pdl[row * DI + colb] = make_float4(dl[0], dl[1], dl[2], dl[3]);
    }
}

// ----------------------------- B/C repack -----------------------------
__global__ __launch_bounds__(256) void repack_kernel()
{
    int id = blockIdx.x * 256 + threadIdx.x;
    if (id >= 2 * NB * LL * 2 * DS) return;
    int n = id & 15;
    int which = (id >> 4) & 1;
    int t = (id >> 5) & (LL - 1);
    int b = (id >> 17) & 1;
    int dir = (id >> 18) & 1;
    float v = g_xdbl[dir][b][t][DR + which * DS + n];
    float* dst = which ? &g_Cc[dir][b][0][0][0] : &g_Bc[dir][b][0][0][0];
    dst[(t >> 2) * (DS*4) + n * 4 + (t & 3)] = v;
}

// ----------------------------- conv+silu: 2 channels x 4 t per thread, fp16 in/out -----------------------------
__global__ __launch_bounds__(256) void conv_silu_kernel(
    const float* __restrict__ cw0, const float* __restrict__ cb0,
    const float* __restrict__ cw1, const float* __restrict__ cb1)
{
    long id = (long)blockIdx.x * 256 + threadIdx.x;
    const long total = (long)2 * NB * (LL/4) * (DI/2);
    if (id >= total) return;
    int dp = (int)(id % (DI/2)); long r = id / (DI/2);
    int t4 = (int)(r % (LL/4)); r /= (LL/4);
    int b = (int)(r % NB); int dir = (int)(r / NB);
    const float* cw = dir ? cw1 : cw0;
    const float* cb = dir ? cb1 : cb0;
    const int d = dp * 2;
    const __half* xi = &g_xi16[dir][b][0][d];
    const int tb = t4 * 4;
    float2 rv[7];
    #pragma unroll
    for (int i = 0; i < 7; i++) {
        int tt = tb - 3 + i;
        rv[i] = (tt >= 0) ? __half22float2(*(const __half2*)&xi[(long)tt * DI])
                          : make_float2(0.f, 0.f);
    }
    float4 w0 = *(const float4*)&cw[d * 4];
    float4 w1 = *(const float4*)&cw[d * 4 + 4];
    float cb0v = cb[d], cb1v = cb[d + 1];
    #pragma unroll
    for (int j = 0; j < 4; j++) {
        float a0 = cb0v + w0.x*rv[j].x + w0.y*rv[j+1].x + w0.z*rv[j+2].x + w0.w*rv[j+3].x;
        float a1 = cb1v + w1.x*rv[j].y + w1.y*rv[j+1].y + w1.z*rv[j+2].y + w1.w*rv[j+3].y;
        float v0 = a0 / (1.f + __expf(-a0));
        float v1 = a1 / (1.f + __expf(-a1));
        *(__half2*)&g_xch16[dir][b][tb + j][d] = __floats2half2_rn(v0, v1);
    }
}

// ===========================================================================
// selective scan + fused gate. Block = 128 threads = 8 d x 16 n; 384 blocks.
// xc read as fp16 (sole copy). R13-style plain __expf recurrence.
// ===========================================================================
#define SCAN_T 64
__global__ __launch_bounds__(128) void scan_kernel(
    const float* __restrict__ Al0, const float* __restrict__ Al1,
    const float* __restrict__ D0,  const float* __restrict__ D1)
{
    __shared__ float s_dl[SCAN_T][8];
    __shared__ float s_xc[SCAN_T][8];
    __shared__ float s_z [SCAN_T][8];
    __shared__ __half s_g[SCAN_T][8];

    const int bx = blockIdx.x;          // 0..383
    const int dgrp = bx % 96;
    const int b = (bx / 96) & 1;
    const int dir = bx / 192;
    const int d0 = dgrp * 8;
    const int tid = threadIdx.x;
    const int n = tid & 15;
    const int dloc = tid >> 4;          // 0..7
    const int d = d0 + dloc;

    const float* Al  = dir ? Al1 : Al0;
    const float* Dpt = dir ? D1 : D0;
    const float Acoef = -__expf(Al[d*DS + n]);
    const float Dv = Dpt[d];

    const float* pdl = &g_delta[dir][b][0][0];
    const __half* pxc = &g_xch16[dir][b][0][0];
    const __half* pz  = &g_z16[dir][b][0][0];
    const float4* pB = (const float4*)&g_Bc[dir][b][0][0][0];
    const float4* pC = (const float4*)&g_Cc[dir][b][0][0][0];
    __half* pg = &g_gate16[dir][b][0][0];

    const int l_tl = tid >> 1;          // 0..63
    const int l_c4 = (tid & 1) * 4;     // 0 or 4

    float h = 0.f;
    for (int t0 = 0; t0 < LL; t0 += SCAN_T) {
        __syncthreads();
        {
            long rbase = (long)(t0 + l_tl) * DI + d0 + l_c4;
            float4 vdl = *(const float4*)&pdl[rbase];
            uint2 vxr = *(const uint2*)&pxc[rbase];
            uint2 vzr = *(const uint2*)&pz[rbase];
            float2 x01 = __half22float2(*(__half2*)&vxr.x);
            float2 x23 = __half22float2(*(__half2*)&vxr.y);
            float2 z01 = __half22float2(*(__half2*)&vzr.x);
            float2 z23 = __half22float2(*(__half2*)&vzr.y);
            *(float4*)&s_dl[l_tl][l_c4] = vdl;
            *(float4*)&s_xc[l_tl][l_c4] = make_float4(x01.x, x01.y, x23.x, x23.y);
            *(float4*)&s_z [l_tl][l_c4] = make_float4(z01.x, z01.y, z23.x, z23.y);
        }
        __syncthreads();
        #pragma unroll 2
        for (int t4 = 0; t4 < SCAN_T/4; t4++) {
            int tt4 = (t0 >> 2) + t4;
            float4 Bv = __ldg(&pB[tt4*16 + n]);
            float4 Cv = __ldg(&pC[tt4*16 + n]);
            float p[4];
            #pragma unroll
            for (int j = 0; j < 4; j++) {
                int tl = t4*4 + j;
                float dl  = s_dl[tl][dloc];
                float xcv = s_xc[tl][dloc];
                float uu = dl * xcv;
                float dA = __expf(dl * Acoef);
                float Bj = (j==0)?Bv.x:(j==1)?Bv.y:(j==2)?Bv.z:Bv.w;
                float Cj = (j==0)?Cv.x:(j==1)?Cv.y:(j==2)?Cv.z:Cv.w;
                h = fmaf(dA, h, uu * Bj);
                p[j] = h * Cj;
            }
            #pragma unroll
            for (int s = 1; s < 16; s <<= 1) {
                p[0] += __shfl_xor_sync(0xffffffffu, p[0], s);
                p[1] += __shfl_xor_sync(0xffffffffu, p[1], s);
                p[2] += __shfl_xor_sync(0xffffffffu, p[2], s);
                p[3] += __shfl_xor_sync(0xffffffffu, p[3], s);
            }
            if (n == 0) {
                #pragma unroll
                for (int j = 0; j < 4; j++) {
                    int tl = t4*4 + j;
                    float zv = s_z[tl][dloc];
                    float yv = p[j] + s_xc[tl][dloc] * Dv;
                    float gv = yv * (zv / (1.f + __expf(-zv)));
                    s_g[tl][dloc] = __float2half(gv);
                }
            }
        }
        __syncthreads();
        #pragma unroll
        for (int q = 0; q < 2; q++) {
            int u = tid + q * 128;          // 0..255 -> 64 rows x 4 half2
            int row = u >> 2, cp = u & 3;
            __half2 v = *(__half2*)&s_g[row][cp*2];
            *(__half2*)&pg[(long)(t0 + row) * DI + d0 + cp*2] = v;
        }
    }
}

// ----------------------------- GLU + partial stats -----------------------------
__global__ __launch_bounds__(256) void glu_kernel()
{
    const int batch = blockIdx.y;
    const int tid = threadIdx.x;
    float lsum = 0.f, lssq = 0.f;
    const float* yc = &g_yc[batch][0][0];
    float* gl = &g_glu[batch][0][0];
    for (int it = 0; it < 128; it++) {
        long e = (long)blockIdx.x * 32768 + (long)it * 256 + tid;
        int t = (int)(e / DM), o = (int)(e % DM);
        float a  = yc[(long)t * (2*DM) + o];
        float bg = yc[(long)t * (2*DM) + DM + o];
        float g = a * (1.f / (1.f + __expf(-bg)));
        gl[e] = g;
        lsum += g; lssq += g * g;
    }
    __shared__ float s1[256], s2[256];
    s1[tid] = lsum; s2[tid] = lssq;
    __syncthreads();
    for (int s = 128; s > 0; s >>= 1) {
        if (tid < s) { s1[tid] += s1[tid+s]; s2[tid] += s2[tid+s]; }
        __syncthreads();
    }
    if (tid == 0) g_part[batch][blockIdx.x] = make_float2(s1[0], s2[0]);
}

__global__ void stats_kernel()
{
    int b = threadIdx.x;
    if (b < NB) {
        float sum = 0.f, ssq = 0.f;
        for (int i = 0; i < 48; i++) { float2 p = g_part[b][i]; sum += p.x; ssq += p.y; }
        const float inv = 1.f / ((float)DM * (float)LL);
        float mu = sum * inv;
        float var = ssq * inv - mu * mu;
        g_stats[b] = make_float2(mu, rsqrtf(var + 1e-5f));
    }
}

// ----------------------------- normalize + transpose to output [b][c][t] -----------------------------
__global__ __launch_bounds__(256) void norm_kernel(
    const float* __restrict__ gnw, const float* __restrict__ gnb,
    float* __restrict__ out)
{
    __shared__ float s[32][33];
    const int b = blockIdx.z;
    const int t0 = blockIdx.x * 32;
    const int c0 = blockIdx.y * 32;
    const int tx = threadIdx.x & 31;
    const int ty = threadIdx.x >> 5;
    #pragma unroll
    for (int j = 0; j < 4; j++) {
        int t = t0 + ty + j*8;
        s[ty + j*8][tx] = g_glu[b][t][c0 + tx];
    }
    __syncthreads();
    float2 st = g_stats[b];
    #pragma unroll
    for (int j = 0; j < 4; j++) {
        int c = c0 + ty + j*8;
        float v = s[tx][ty + j*8];
        out[((long)b * DM + c) * LL + t0 + tx] = (v - st.x) * st.y * gnw[c] + gnb[c];
    }
}

// ----------------------------- launch -----------------------------
extern "C" void kernel_launch(void* const* d_in, const int* in_sizes, int n_in,
                              void* d_out, int out_size)
{
    (void)in_sizes; (void)n_in; (void)out_size;
    const float* x        = (const float*)d_in[0];
    const float* f_in_w   = (const float*)d_in[1];
    const float* f_conv_w = (const float*)d_in[2];
    const float* f_conv_b = (const float*)d_in[3];
    const float* f_xproj  = (const float*)d_in[4];
    const float* f_dt_w   = (const float*)d_in[5];
    const float* f_dt_b   = (const float*)d_in[6];
    const float* f_A_log  = (const float*)d_in[7];
    const float* f_D      = (const float*)d_in[8];
    const float* f_out_w  = (const float*)d_in[9];
    const float* b_in_w   = (const float*)d_in[10];
    const float* b_conv_w = (const float*)d_in[11];
    const float* b_conv_b = (const float*)d_in[12];
    const float* b_xproj  = (const float*)d_in[13];
    const float* b_dt_w   = (const float*)d_in[14];
    const float* b_dt_b   = (const float*)d_in[15];
    const float* b_A_log  = (const float*)d_in[16];
    const float* b_D      = (const float*)d_in[17];
    const float* b_out_w  = (const float*)d_in[18];
    const float* c_w      = (const float*)d_in[19];
    const float* c_b      = (const float*)d_in[20];
    const float* gn_w     = (const float*)d_in[21];
    const float* gn_b     = (const float*)d_in[22];
    float* out = (float*)d_out;

    float *pxdbl, *pyc;
    cudaGetSymbolAddress((void**)&pxdbl, g_xdbl);
    cudaGetSymbolAddress((void**)&pyc,   g_yc);
    __half *pxT16, *pinw16, *pxi16, *pz16, *pxch16, *pxpw16, *pgate16, *poutw16, *pycat16, *pcw16;
    cudaGetSymbolAddress((void**)&pxT16,   g_xT16);
    cudaGetSymbolAddress((void**)&pinw16,  g_inw16);
    cudaGetSymbolAddress((void**)&pxi16,   g_xi16);
    cudaGetSymbolAddress((void**)&pz16,    g_z16);
    cudaGetSymbolAddress((void**)&pxch16,  g_xch16);
    cudaGetSymbolAddress((void**)&pxpw16,  g_xpw16);
    cudaGetSymbolAddress((void**)&pgate16, g_gate16);
    cudaGetSymbolAddress((void**)&poutw16, g_outw16);
    cudaGetSymbolAddress((void**)&pycat16, g_ycat16);
    cudaGetSymbolAddress((void**)&pcw16,   g_cw16);

    static bool attr_set = false;
    if (!attr_set) {
        cudaFuncSetAttribute(hmma16, cudaFuncAttributeMaxDynamicSharedMemorySize, HMMA16_SMEM);
        attr_set = true;
    }

    const long INW  = (long)(2*DI) * DM;
    const long OUTW = (long)DM * DI;

    // 0) fused prep
    prep_kernel<<<8064, 256>>>(x, f_in_w, b_in_w, f_out_w, b_out_w, c_w, f_xproj, b_xproj);

    // 1) in-projection: z=dir*2+b, M=4096, N=1536, K=384 -> fp16 xi/z split
    hmma16<<<dim3(24, 32, 4), 256, HMMA16_SMEM>>>(
        pxT16, DM, (long)LL*DM,
        pinw16, pinw16 + INW, nullptr,
        nullptr, pxi16, pz16, DI, (long)LL*DI, DM, 2*DI, 0);

    // 2) depthwise causal conv + silu (fp16 out only)
    {
        long total = (long)2 * NB * (LL/4) * (DI/2);
        conv_silu_kernel<<<(unsigned)((total + 255) / 256), 256>>>(f_conv_w, f_conv_b, b_conv_w, b_conv_b);
    }

    // 3) x-projection: z=dir, M=8192, N=64(pad), K=768 -> fp32 g_xdbl
    hmma16<<<dim3(1, 64, 2), 256, HMMA16_SMEM>>>(
        pxch16, DI, (long)NB*LL*DI,
        pxpw16, pxpw16 + 64*DI, nullptr,
        pxdbl, nullptr, nullptr, XW, (long)NB*LL*XW, DI, XW, 1);

    // 4) delta; 4b) repack; 5) fused scan+gate (plain __expf; fp16 xc)
    delta_gemm<<<dim3(DI/64, (NB*LL)/64, 2), 256>>>(f_dt_w, f_dt_b, b_dt_w, b_dt_b);
    repack_kernel<<<2048, 256>>>();
    scan_kernel<<<384, 128>>>(f_A_log, b_A_log, f_D, b_D);

    // 6) out-projection: z=dir, M=8192, N=384, K=768 -> fp16 ycat col halves
    hmma16<<<dim3(6, 64, 2), 256, HMMA16_SMEM>>>(
        pgate16, DI, (long)NB*LL*DI,
        poutw16, poutw16 + OUTW, nullptr,
        nullptr, pycat16, nullptr, 2*DM, (long)DM, DI, DM, 1);

    // 7) final 1x1 conv: M=8192, N=768, K=768, bias -> fp32 g_yc
    hmma16<<<dim3(12, 64, 1), 256, HMMA16_SMEM>>>(
        pycat16, 2*DM, 0L,
        pcw16, pcw16, c_b,
        pyc, nullptr, nullptr, 2*DM, 0L, 2*DM, 2*DM, 1);

    // 8) GLU + stats + normalize
    glu_kernel<<<dim3(48, 2), 256>>>();
    stats_kernel<<<1, 32>>>();
    norm_kernel<<<dim3(LL/32, DM/32, NB), 256>>>(gn_w, gn_b, out);
}

// round 17
// speedup vs baseline: 1.1952x; 1.0266x over previous
#include <cuda_runtime.h>
#include <cuda_fp16.h>
#include <cstdint>

#define LL 4096
#define DM 384
#define DI 768
#define DS 16
#define DR 24
#define NB 2
#define XW (DR + 2*DS)   // 56

// ----------------------------- scratch (device globals) -----------------------------
__device__ float g_xdbl [2][NB][LL][XW];     // x-proj output (dt | B | C)
__device__ float g_delta[2][NB][LL][DI];     // softplus(dt@dtw+b)
__device__ float g_Bc   [2][NB][LL/4][DS][4];
__device__ float g_Cc   [2][NB][LL/4][DS][4];
__device__ float g_yc   [NB][LL][2*DM];
__device__ float g_glu  [NB][LL][DM];
__device__ float2 g_part[NB][64];
__device__ float2 g_stats[NB];

// fp16 buffers
__device__ __align__(16) __half g_xi16  [2][NB][LL][DI];  // inproj xi half (pre-conv)
__device__ __align__(16) __half g_z16   [2][NB][LL][DI];  // inproj z half
__device__ __align__(16) __half g_xT16  [NB][LL][DM];
__device__ __align__(16) __half g_inw16 [2][2*DI][DM];
__device__ __align__(16) __half g_xch16 [2][NB][LL][DI];  // conv+silu output (sole copy)
__device__ __align__(16) __half g_xpw16 [2][64][DI];      // xproj W padded 56->64
__device__ __align__(16) __half g_gate16[2][NB][LL][DI];  // written by fused scan
__device__ __align__(16) __half g_outw16[2][DM][DI];
__device__ __align__(16) __half g_ycat16[NB][LL][2*DM];
__device__ __align__(16) __half g_cw16  [2*DM][2*DM];

// ----------------------------- helpers -----------------------------
__device__ __forceinline__ uint32_t smem_to_u32(const void* p) {
    uint32_t a;
    asm("{ .reg .u64 t; cvta.to.shared.u64 t, %1; cvt.u32.u64 %0, t; }" : "=r"(a) : "l"(p));
    return a;
}
__device__ __forceinline__ void ldsm4(uint32_t* r, uint32_t addr){
    asm volatile("ldmatrix.sync.aligned.m8n8.x4.shared.b16 {%0,%1,%2,%3}, [%4];"
        : "=r"(r[0]), "=r"(r[1]), "=r"(r[2]), "=r"(r[3]) : "r"(addr));
}
__device__ __forceinline__ void mma_f16(float* c, const uint32_t* a, const uint32_t* b){
    asm volatile("mma.sync.aligned.m16n8k16.row.col.f32.f16.f16.f32 "
        "{%0,%1,%2,%3}, {%4,%5,%6,%7}, {%8,%9}, {%0,%1,%2,%3};"
        : "+f"(c[0]), "+f"(c[1]), "+f"(c[2]), "+f"(c[3])
        : "r"(a[0]), "r"(a[1]), "r"(a[2]), "r"(a[3]), "r"(b[0]), "r"(b[1]));
}
__device__ __forceinline__ void cpasync16(uint32_t s, const void* g){
    asm volatile("cp.async.cg.shared.global [%0], [%1], 16;" :: "r"(s), "l"(g));
}
#define CP_COMMIT() asm volatile("cp.async.commit_group;" ::: "memory")
template<int N> __device__ __forceinline__ void cpwait(){
    asm volatile("cp.async.wait_group %0;" :: "n"(N) : "memory");
}

// ===========================================================================
// fp16 HMMA GEMM: tile 128x64, K-chunk 64, 4-stage cp.async pipeline.
// mode 0 (inproj): z=dir*2+b; A+=(z&1)*Az; rev=z>>1; W=(z>>1)?W1:W0;
//                  split fp16 output: col<DI -> Ch (xi), else Ch2 (z), stride DI.
// mode 1 (other) : A+z*Az, rev=0, W=z?W1:W0; Ch fp16 out else Cf fp32 (+bias).
// ===========================================================================
#define SMF_W 16384u
#define SMF_STAGE 24576u
#define HMMA16_SMEM (4 * SMF_STAGE)   // 98304

__device__ __forceinline__ void load_chunk16(
    uint32_t bufb, const __half* __restrict__ A, const __half* __restrict__ W,
    int lda, int ldw, int k0, int row0, int col0, int rev, int tid)
{
    #pragma unroll
    for (int i = 0; i < 4; i++) {
        int u = i * 256 + tid;
        int rr = u >> 3, c8 = u & 7;
        int ar = rev ? (LL - 1 - (row0 + rr)) : (row0 + rr);
        uint32_t off = ((uint32_t)(rr * 128 + c8 * 16)) ^ ((uint32_t)(rr & 7) << 4);
        cpasync16(bufb + off, A + (long)ar * lda + k0 + c8 * 8);
    }
    #pragma unroll
    for (int i = 0; i < 2; i++) {
        int u = i * 256 + tid;
        int rr = u >> 3, c8 = u & 7;
        uint32_t off = ((uint32_t)(rr * 128 + c8 * 16)) ^ ((uint32_t)(rr & 7) << 4);
        cpasync16(bufb + SMF_W + off, W + (long)(col0 + rr) * ldw + k0 + c8 * 8);
    }
}

__global__ __launch_bounds__(256, 2) void hmma16(
    const __half* __restrict__ A, int lda, long Az,
    const __half* __restrict__ W0, const __half* __restrict__ W1,
    const float* __restrict__ bias,
    float* __restrict__ Cf, __half* __restrict__ Ch, __half* __restrict__ Ch2,
    int ldc, long Cz, int K, int ncols, int mode)
{
    extern __shared__ __align__(16) char sm[];
    const uint32_t sb = smem_to_u32(sm);

    const int tid  = threadIdx.x;
    const int lane = tid & 31;
    const int warp = tid >> 5;
    const int m0w = (warp >> 1) * 32;
    const int n0w = (warp & 1) * 32;

    const int z = blockIdx.z;
    const int row0 = blockIdx.y * 128;
    const int col0 = blockIdx.x * 64;

    const __half *pA, *pW;
    int rev = 0;
    if (mode == 0) {
        pA = A + (long)(z & 1) * Az;
        rev = z >> 1;
        pW = (z >> 1) ? W1 : W0;
    } else {
        pA = A + (long)z * Az;
        pW = z ? W1 : W0;
    }

    float acc[2][4][4];
    #pragma unroll
    for (int i = 0; i < 2; i++)
        #pragma unroll
        for (int j = 0; j < 4; j++)
            #pragma unroll
            for (int q = 0; q < 4; q++) acc[i][j][q] = 0.f;

    const int lj = lane >> 3;
    const int lr = lane & 7;
    const int nc = K >> 6;

    load_chunk16(sb,             pA, pW, lda, K, 0,  row0, col0, rev, tid); CP_COMMIT();
    load_chunk16(sb + SMF_STAGE, pA, pW, lda, K, 64, row0, col0, rev, tid); CP_COMMIT();

    for (int c = 0; c < nc; c++) {
        if (c + 2 < nc) {
            load_chunk16(sb + ((c + 2) & 3) * SMF_STAGE, pA, pW, lda, K,
                         (c + 2) << 6, row0, col0, rev, tid);
            CP_COMMIT();
            cpwait<2>();
        } else if (c + 1 < nc) {
            cpwait<1>();
        } else {
            cpwait<0>();
        }
        __syncthreads();
        const uint32_t bufb = sb + (c & 3) * SMF_STAGE;
        #pragma unroll
        for (int ks = 0; ks < 4; ks++) {
            const int kb = ks * 16;
            uint32_t af[2][4], bf[2][4];
            #pragma unroll
            for (int mh = 0; mh < 2; mh++) {
                int row = m0w + mh * 16 + ((lj & 1) << 3) + lr;
                int kc  = kb + ((lj >> 1) << 3);
                uint32_t off = ((uint32_t)(row * 128 + kc * 2)) ^ ((uint32_t)(row & 7) << 4);
                ldsm4(af[mh], bufb + off);
            }
            #pragma unroll
            for (int np = 0; np < 2; np++) {
                int row = n0w + np * 16 + ((lj >> 1) << 3) + lr;
                int kc  = kb + ((lj & 1) << 3);
                uint32_t off = ((uint32_t)(row * 128 + kc * 2)) ^ ((uint32_t)(row & 7) << 4);
                ldsm4(bf[np], bufb + SMF_W + off);
            }
            #pragma unroll
            for (int mh = 0; mh < 2; mh++) {
                #pragma unroll
                for (int ng = 0; ng < 4; ng++)
                    mma_f16(acc[mh][ng], af[mh], &bf[ng >> 1][(ng & 1) * 2]);
            }
        }
    }

    // ---- epilogue ----
    const int g = lane >> 2, tig = lane & 3;
    if (mode == 0) {
        __half* Xi = Ch  + (long)z * Cz;
        __half* Zb = Ch2 + (long)z * Cz;
        #pragma unroll
        for (int mh = 0; mh < 2; mh++) {
            #pragma unroll
            for (int ng = 0; ng < 4; ng++) {
                int row = row0 + m0w + mh * 16 + g;
                int col = col0 + n0w + ng * 8 + tig * 2;
                __half* T = (col < DI) ? Xi : Zb;
                int cc = (col < DI) ? col : col - DI;
                *(__half2*)&T[(long)row * DI + cc] =
                    __floats2half2_rn(acc[mh][ng][0], acc[mh][ng][1]);
                *(__half2*)&T[(long)(row + 8) * DI + cc] =
                    __floats2half2_rn(acc[mh][ng][2], acc[mh][ng][3]);
            }
        }
    } else if (Ch) {
        __half* Cb = Ch + (long)z * Cz;
        #pragma unroll
        for (int mh = 0; mh < 2; mh++) {
            #pragma unroll
            for (int ng = 0; ng < 4; ng++) {
                int row = row0 + m0w + mh * 16 + g;
                int col = col0 + n0w + ng * 8 + tig * 2;
                if (col < ncols) {
                    *(__half2*)&Cb[(long)row * ldc + col] =
                        __floats2half2_rn(acc[mh][ng][0], acc[mh][ng][1]);
                    *(__half2*)&Cb[(long)(row + 8) * ldc + col] =
                        __floats2half2_rn(acc[mh][ng][2], acc[mh][ng][3]);
                }
            }
        }
    } else {
        float* Cb = Cf + (long)z * Cz;
        #pragma unroll
        for (int mh = 0; mh < 2; mh++) {
            #pragma unroll
            for (int ng = 0; ng < 4; ng++) {
                int row = row0 + m0w + mh * 16 + g;
                int col = col0 + n0w + ng * 8 + tig * 2;
                if (col < ncols) {
                    float b0 = 0.f, b1 = 0.f;
                    if (bias) { b0 = bias[col]; b1 = bias[col + 1]; }
                    *(float2*)&Cb[(long)row * ldc + col] =
                        make_float2(acc[mh][ng][0] + b0, acc[mh][ng][1] + b1);
                    *(float2*)&Cb[(long)(row + 8) * ldc + col] =
                        make_float2(acc[mh][ng][2] + b0, acc[mh][ng][3] + b1);
                }
            }
        }
    }
}

// ===========================================================================
// fused prep: x transpose + 5 weight converts + xproj pad, single launch.
// ===========================================================================
__global__ __launch_bounds__(256) void prep_kernel(
    const float* __restrict__ x,
    const float* __restrict__ f_in_w, const float* __restrict__ b_in_w,
    const float* __restrict__ f_out_w, const float* __restrict__ b_out_w,
    const float* __restrict__ c_w,
    const float* __restrict__ f_xproj, const float* __restrict__ b_xproj)
{
    const int bid = blockIdx.x;
    const int tid = threadIdx.x;
    if (bid < 3072) {
        __shared__ float s[32][33];
        const int t0 = (bid & 127) * 32;
        const int c0 = ((bid >> 7) % 12) * 32;
        const int b = bid / 1536;
        const int tx = tid & 31;
        const int ty = tid >> 5;
        #pragma unroll
        for (int j = 0; j < 4; j++)
            s[ty + j*8][tx] = x[((long)b * DM + c0 + ty + j*8) * LL + t0 + tx];
        __syncthreads();
        #pragma unroll
        for (int j = 0; j < 4; j++)
            g_xT16[b][t0 + ty + j*8][c0 + tx] = __float2half(s[tx][ty + j*8]);
        return;
    }
    int r = bid - 3072;
    const float* src = nullptr;
    __half* dst = nullptr;
    if (r < 1152)      { src = f_in_w;  dst = &g_inw16[0][0][0]; }
    else if (r < 2304) { src = b_in_w;  dst = &g_inw16[1][0][0]; r -= 1152; }
    else if (r < 2880) { src = f_out_w; dst = &g_outw16[0][0][0]; r -= 2304; }
    else if (r < 3456) { src = b_out_w; dst = &g_outw16[1][0][0]; r -= 2880; }
    else if (r < 4608) { src = c_w;     dst = &g_cw16[0][0];      r -= 3456; }
    else {
        r -= 4608;
        int i = r * 256 + tid;
        int k = i % DI;
        int row = (i / DI) & 63;
        int dir = i / (64 * DI);
        const float* w = dir ? b_xproj : f_xproj;
        float v = (row < XW) ? w[row * DI + k] : 0.f;
        g_xpw16[dir][row][k] = __float2half(v);
        return;
    }
    int i = r * 256 + tid;
    float2 v = *(const float2*)&src[i * 2];
    ((__half2*)dst)[i] = __floats2half2_rn(v.x, v.y);
}

// ----------------------------- f32x2 helpers (delta_gemm) -----------------------------
__device__ __forceinline__ unsigned long long dup2(float x){
    unsigned long long r; asm("mov.b64 %0, {%1, %1};" : "=l"(r) : "f"(x)); return r;
}
__device__ __forceinline__ void ffma2(unsigned long long &d, unsigned long long a, unsigned long long b){
    asm("fma.rn.f32x2 %0, %1, %2, %0;" : "+l"(d) : "l"(a), "l"(b));
}
__device__ __forceinline__ float2 unpk2(unsigned long long v){
    float2 f; asm("mov.b64 {%0, %1}, %2;" : "=f"(f.x), "=f"(f.y) : "l"(v)); return f;
}

// ===========================================================================
// delta GEMM: delta = softplus(dt @ dtw^T + dtb)
// ===========================================================================
__global__ __launch_bounds__(256) void delta_gemm(
    const float* __restrict__ dtw0, const float* __restrict__ dtb0,
    const float* __restrict__ dtw1, const float* __restrict__ dtb1)
{
    __shared__ float As[DR][64];
    __shared__ float Bs[DR][64];
    const int dir = blockIdx.z;
    const float* Ab  = &g_xdbl[dir][0][0][0];
    float* pdl = &g_delta[dir][0][0][0];
    const float* dtw = dir ? dtw1 : dtw0;
    const float* dtb = dir ? dtb1 : dtb0;
    const int row0 = blockIdx.y * 64;
    const int col0 = blockIdx.x * 64;
    const int tid = threadIdx.x;
    const int tx = tid & 15, ty = tid >> 4;

    for (int i = tid; i < 64 * DR; i += 256) {
        int r = i / DR, k = i % DR;
        As[k][r] = Ab[(long)(row0 + r) * XW + k];
        Bs[k][r] = dtw[(long)(col0 + r) * DR + k];
    }
    __syncthreads();

    unsigned long long acc[2][4];
    #pragma unroll
    for (int i = 0; i < 2; i++)
        #pragma unroll
        for (int j = 0; j < 4; j++) acc[i][j] = 0ull;

    #pragma unroll
    for (int k = 0; k < DR; k++) {
        unsigned long long a01 = *(const unsigned long long*)&As[k][ty*4];
        unsigned long long a23 = *(const unsigned long long*)&As[k][ty*4+2];
        float4 bv = *(const float4*)&Bs[k][tx*4];
        unsigned long long b0 = dup2(bv.x), b1 = dup2(bv.y), b2 = dup2(bv.z), b3 = dup2(bv.w);
        ffma2(acc[0][0], a01, b0); ffma2(acc[0][1], a01, b1);
        ffma2(acc[0][2], a01, b2); ffma2(acc[0][3], a01, b3);
        ffma2(acc[1][0], a23, b0); ffma2(acc[1][1], a23, b1);
        ffma2(acc[1][2], a23, b2); ffma2(acc[1][3], a23, b3);
    }
    const int colb = col0 + tx*4;
    float4 bias4 = *(const float4*)&dtb[colb];
    float bsv[4] = {bias4.x, bias4.y, bias4.z, bias4.w};
    float out[4][4];
    #pragma unroll
    for (int i = 0; i < 2; i++)
        #pragma unroll
        for (int j = 0; j < 4; j++) {
            float2 f = unpk2(acc[i][j]);
            out[2*i][j] = f.x; out[2*i+1][j] = f.y;
        }
    #pragma unroll
    for (int r = 0; r < 4; r++) {
        long row = row0 + ty*4 + r;
        float dl[4];
        #pragma unroll
        for (int j = 0; j < 4; j++) {
            float s = out[r][j] + bsv[j];
            dl[j] = fmaxf(s, 0.f) + log1pf(__expf(-fabsf(s)));
        }
        *(float4*)&pdl[row * DI + colb] = make_float4(dl[0], dl[1], dl[2], dl[3]);
    }
}

// ----------------------------- B/C repack -----------------------------
__global__ __launch_bounds__(256) void repack_kernel()
{
    int id = blockIdx.x * 256 + threadIdx.x;
    if (id >= 2 * NB * LL * 2 * DS) return;
    int n = id & 15;
    int which = (id >> 4) & 1;
    int t = (id >> 5) & (LL - 1);
    int b = (id >> 17) & 1;
    int dir = (id >> 18) & 1;
    float v = g_xdbl[dir][b][t][DR + which * DS + n];
    float* dst = which ? &g_Cc[dir][b][0][0][0] : &g_Bc[dir][b][0][0][0];
    dst[(t >> 2) * (DS*4) + n * 4 + (t & 3)] = v;
}

// ----------------------------- conv+silu: 2 channels x 4 t per thread, fp16 in/out -----------------------------
__global__ __launch_bounds__(256) void conv_silu_kernel(
    const float* __restrict__ cw0, const float* __restrict__ cb0,
    const float* __restrict__ cw1, const float* __restrict__ cb1)
{
    long id = (long)blockIdx.x * 256 + threadIdx.x;
    const long total = (long)2 * NB * (LL/4) * (DI/2);
    if (id >= total) return;
    int dp = (int)(id % (DI/2)); long r = id / (DI/2);
    int t4 = (int)(r % (LL/4)); r /= (LL/4);
    int b = (int)(r % NB); int dir = (int)(r / NB);
    const float* cw = dir ? cw1 : cw0;
    const float* cb = dir ? cb1 : cb0;
    const int d = dp * 2;
    const __half* xi = &g_xi16[dir][b][0][d];
    const int tb = t4 * 4;
    float2 rv[7];
    #pragma unroll
    for (int i = 0; i < 7; i++) {
        int tt = tb - 3 + i;
        rv[i] = (tt >= 0) ? __half22float2(*(const __half2*)&xi[(long)tt * DI])
                          : make_float2(0.f, 0.f);
    }
    float4 w0 = *(const float4*)&cw[d * 4];
    float4 w1 = *(const float4*)&cw[d * 4 + 4];
    float cb0v = cb[d], cb1v = cb[d + 1];
    #pragma unroll
    for (int j = 0; j < 4; j++) {
        float a0 = cb0v + w0.x*rv[j].x + w0.y*rv[j+1].x + w0.z*rv[j+2].x + w0.w*rv[j+3].x;
        float a1 = cb1v + w1.x*rv[j].y + w1.y*rv[j+1].y + w1.z*rv[j+2].y + w1.w*rv[j+3].y;
        float v0 = a0 / (1.f + __expf(-a0));
        float v1 = a1 / (1.f + __expf(-a1));
        *(__half2*)&g_xch16[dir][b][tb + j][d] = __floats2half2_rn(v0, v1);
    }
}

// ===========================================================================
// selective scan v3 + fused gate. Block = 128 threads = 8 d x 16 n; 384 blocks.
// SCAN_T=128 chunks, register double-buffered staging (global loads for chunk
// c+1 issued during chunk c compute), gate output stored at loop top (overlap).
// ===========================================================================
#define SCAN_T 128
__global__ __launch_bounds__(128) void scan_kernel(
    const float* __restrict__ Al0, const float* __restrict__ Al1,
    const float* __restrict__ D0,  const float* __restrict__ D1)
{
    __shared__ float s_dl[SCAN_T][8];
    __shared__ float s_xc[SCAN_T][8];
    __shared__ float s_z [SCAN_T][8];
    __shared__ __half s_g[SCAN_T][8];

    const int bx = blockIdx.x;          // 0..383
    const int dgrp = bx % 96;
    const int b = (bx / 96) & 1;
    const int dir = bx / 192;
    const int d0 = dgrp * 8;
    const int tid = threadIdx.x;
    const int n = tid & 15;
    const int dloc = tid >> 4;          // 0..7
    const int d = d0 + dloc;

    const float* Al  = dir ? Al1 : Al0;
    const float* Dpt = dir ? D1 : D0;
    const float Acoef = -__expf(Al[d*DS + n]);
    const float Dv = Dpt[d];

    const float* pdl = &g_delta[dir][b][0][0];
    const __half* pxc = &g_xch16[dir][b][0][0];
    const __half* pz  = &g_z16[dir][b][0][0];
    const float4* pB = (const float4*)&g_Bc[dir][b][0][0][0];
    const float4* pC = (const float4*)&g_Cc[dir][b][0][0][0];
    __half* pg = &g_gate16[dir][b][0][0];

    // staging layout: thread covers rows sr and sr+64, cols sc..sc+3
    const int sr = tid >> 1;            // 0..63
    const int sc = (tid & 1) * 4;       // 0 or 4

    float4 rdl[2];
    uint2  rxc[2], rz[2];
    {
        #pragma unroll
        for (int q = 0; q < 2; q++) {
            long rbase = (long)(sr + q*64) * DI + d0 + sc;
            rdl[q] = *(const float4*)&pdl[rbase];
            rxc[q] = *(const uint2*)&pxc[rbase];
            rz[q]  = *(const uint2*)&pz[rbase];
        }
    }

    float h = 0.f;
    for (int t0 = 0; t0 < LL; t0 += SCAN_T) {
        __syncthreads();   // prior compute done: s_* consumable, s_g final
        if (t0 > 0) {
            // write previous chunk's gate output (overlaps with staging)
            #pragma unroll
            for (int q = 0; q < 4; q++) {
                int u = tid + q * 128;          // 512 half2 = 128 rows x 4 half2
                int row = u >> 2, cp = u & 3;
                __half2 v = *(__half2*)&s_g[row][cp*2];
                *(__half2*)&pg[(long)(t0 - SCAN_T + row) * DI + d0 + cp*2] = v;
            }
        }
        // stage registers -> smem
        #pragma unroll
        for (int q = 0; q < 2; q++) {
            int row = sr + q*64;
            *(float4*)&s_dl[row][sc] = rdl[q];
            float2 x01 = __half22float2(*(__half2*)&rxc[q].x);
            float2 x23 = __half22float2(*(__half2*)&rxc[q].y);
            float2 z01 = __half22float2(*(__half2*)&rz[q].x);
            float2 z23 = __half22float2(*(__half2*)&rz[q].y);
            *(float4*)&s_xc[row][sc] = make_float4(x01.x, x01.y, x23.x, x23.y);
            *(float4*)&s_z [row][sc] = make_float4(z01.x, z01.y, z23.x, z23.y);
        }
        __syncthreads();
        // issue next chunk's global loads (consumed at next staging)
        if (t0 + SCAN_T < LL) {
            #pragma unroll
            for (int q = 0; q < 2; q++) {
                long rbase = (long)(t0 + SCAN_T + sr + q*64) * DI + d0 + sc;
                rdl[q] = *(const float4*)&pdl[rbase];
                rxc[q] = *(const uint2*)&pxc[rbase];
                rz[q]  = *(const uint2*)&pz[rbase];
            }
        }
        // compute chunk
        #pragma unroll 2
        for (int t4 = 0; t4 < SCAN_T/4; t4++) {
            int tt4 = (t0 >> 2) + t4;
            float4 Bv = __ldg(&pB[tt4*16 + n]);
            float4 Cv = __ldg(&pC[tt4*16 + n]);
            float p[4];
            #pragma unroll
            for (int j = 0; j < 4; j++) {
                int tl = t4*4 + j;
                float dl  = s_dl[tl][dloc];
                float xcv = s_xc[tl][dloc];
                float uu = dl * xcv;
                float dA = __expf(dl * Acoef);
                float Bj = (j==0)?Bv.x:(j==1)?Bv.y:(j==2)?Bv.z:Bv.w;
                float Cj = (j==0)?Cv.x:(j==1)?Cv.y:(j==2)?Cv.z:Cv.w;
                h = fmaf(dA, h, uu * Bj);
                p[j] = h * Cj;
            }
            #pragma unroll
            for (int s = 1; s < 16; s <<= 1) {
                p[0] += __shfl_xor_sync(0xffffffffu, p[0], s);
                p[1] += __shfl_xor_sync(0xffffffffu, p[1], s);
                p[2] += __shfl_xor_sync(0xffffffffu, p[2], s);
                p[3] += __shfl_xor_sync(0xffffffffu, p[3], s);
            }
            if (n == 0) {
                #pragma unroll
                for (int j = 0; j < 4; j++) {
                    int tl = t4*4 + j;
                    float zv = s_z[tl][dloc];
                    float yv = p[j] + s_xc[tl][dloc] * Dv;
                    float gv = yv * (zv / (1.f + __expf(-zv)));
                    s_g[tl][dloc] = __float2half(gv);
                }
            }
        }
    }
    __syncthreads();
    // final chunk's gate output
    #pragma unroll
    for (int q = 0; q < 4; q++) {
        int u = tid + q * 128;
        int row = u >> 2, cp = u & 3;
        __half2 v = *(__half2*)&s_g[row][cp*2];
        *(__half2*)&pg[(long)(LL - SCAN_T + row) * DI + d0 + cp*2] = v;
    }
}

// ----------------------------- GLU + partial stats -----------------------------
__global__ __launch_bounds__(256) void glu_kernel()
{
    const int batch = blockIdx.y;
    const int tid = threadIdx.x;
    float lsum = 0.f, lssq = 0.f;
    const float* yc = &g_yc[batch][0][0];
    float* gl = &g_glu[batch][0][0];
    for (int it = 0; it < 128; it++) {
        long e = (long)blockIdx.x * 32768 + (long)it * 256 + tid;
        int t = (int)(e / DM), o = (int)(e % DM);
        float a  = yc[(long)t * (2*DM) + o];
        float bg = yc[(long)t * (2*DM) + DM + o];
        float g = a * (1.f / (1.f + __expf(-bg)));
        gl[e] = g;
        lsum += g; lssq += g * g;
    }
    __shared__ float s1[256], s2[256];
    s1[tid] = lsum; s2[tid] = lssq;
    __syncthreads();
    for (int s = 128; s > 0; s >>= 1) {
        if (tid < s) { s1[tid] += s1[tid+s]; s2[tid] += s2[tid+s]; }
        __syncthreads();
    }
    if (tid == 0) g_part[batch][blockIdx.x] = make_float2(s1[0], s2[0]);
}

__global__ void stats_kernel()
{
    int b = threadIdx.x;
    if (b < NB) {
        float sum = 0.f, ssq = 0.f;
        for (int i = 0; i < 48; i++) { float2 p = g_part[b][i]; sum += p.x; ssq += p.y; }
        const float inv = 1.f / ((float)DM * (float)LL);
        float mu = sum * inv;
        float var = ssq * inv - mu * mu;
        g_stats[b] = make_float2(mu, rsqrtf(var + 1e-5f));
    }
}

// ----------------------------- normalize + transpose to output [b][c][t] -----------------------------
__global__ __launch_bounds__(256) void norm_kernel(
    const float* __restrict__ gnw, const float* __restrict__ gnb,
    float* __restrict__ out)
{
    __shared__ float s[32][33];
    const int b = blockIdx.z;
    const int t0 = blockIdx.x * 32;
    const int c0 = blockIdx.y * 32;
    const int tx = threadIdx.x & 31;
    const int ty = threadIdx.x >> 5;
    #pragma unroll
    for (int j = 0; j < 4; j++) {
        int t = t0 + ty + j*8;
        s[ty + j*8][tx] = g_glu[b][t][c0 + tx];
    }
    __syncthreads();
    float2 st = g_stats[b];
    #pragma unroll
    for (int j = 0; j < 4; j++) {
        int c = c0 + ty + j*8;
        float v = s[tx][ty + j*8];
        out[((long)b * DM + c) * LL + t0 + tx] = (v - st.x) * st.y * gnw[c] + gnb[c];
    }
}

// ----------------------------- launch -----------------------------
extern "C" void kernel_launch(void* const* d_in, const int* in_sizes, int n_in,
                              void* d_out, int out_size)
{
    (void)in_sizes; (void)n_in; (void)out_size;
    const float* x        = (const float*)d_in[0];
    const float* f_in_w   = (const float*)d_in[1];
    const float* f_conv_w = (const float*)d_in[2];
    const float* f_conv_b = (const float*)d_in[3];
    const float* f_xproj  = (const float*)d_in[4];
    const float* f_dt_w   = (const float*)d_in[5];
    const float* f_dt_b   = (const float*)d_in[6];
    const float* f_A_log  = (const float*)d_in[7];
    const float* f_D      = (const float*)d_in[8];
    const float* f_out_w  = (const float*)d_in[9];
    const float* b_in_w   = (const float*)d_in[10];
    const float* b_conv_w = (const float*)d_in[11];
    const float* b_conv_b = (const float*)d_in[12];
    const float* b_xproj  = (const float*)d_in[13];
    const float* b_dt_w   = (const float*)d_in[14];
    const float* b_dt_b   = (const float*)d_in[15];
    const float* b_A_log  = (const float*)d_in[16];
    const float* b_D      = (const float*)d_in[17];
    const float* b_out_w  = (const float*)d_in[18];
    const float* c_w      = (const float*)d_in[19];
    const float* c_b      = (const float*)d_in[20];
    const float* gn_w     = (const float*)d_in[21];
    const float* gn_b     = (const float*)d_in[22];
    float* out = (float*)d_out;

    float *pxdbl, *pyc;
    cudaGetSymbolAddress((void**)&pxdbl, g_xdbl);
    cudaGetSymbolAddress((void**)&pyc,   g_yc);
    __half *pxT16, *pinw16, *pxi16, *pz16, *pxch16, *pxpw16, *pgate16, *poutw16, *pycat16, *pcw16;
    cudaGetSymbolAddress((void**)&pxT16,   g_xT16);
    cudaGetSymbolAddress((void**)&pinw16,  g_inw16);
    cudaGetSymbolAddress((void**)&pxi16,   g_xi16);
    cudaGetSymbolAddress((void**)&pz16,    g_z16);
    cudaGetSymbolAddress((void**)&pxch16,  g_xch16);
    cudaGetSymbolAddress((void**)&pxpw16,  g_xpw16);
    cudaGetSymbolAddress((void**)&pgate16, g_gate16);
    cudaGetSymbolAddress((void**)&poutw16, g_outw16);
    cudaGetSymbolAddress((void**)&pycat16, g_ycat16);
    cudaGetSymbolAddress((void**)&pcw16,   g_cw16);

    static bool attr_set = false;
    if (!attr_set) {
        cudaFuncSetAttribute(hmma16, cudaFuncAttributeMaxDynamicSharedMemorySize, HMMA16_SMEM);
        attr_set = true;
    }

    const long INW  = (long)(2*DI) * DM;
    const long OUTW = (long)DM * DI;

    // 0) fused prep
    prep_kernel<<<8064, 256>>>(x, f_in_w, b_in_w, f_out_w, b_out_w, c_w, f_xproj, b_xproj);

    // 1) in-projection: z=dir*2+b, M=4096, N=1536, K=384 -> fp16 xi/z split
    hmma16<<<dim3(24, 32, 4), 256, HMMA16_SMEM>>>(
        pxT16, DM, (long)LL*DM,
        pinw16, pinw16 + INW, nullptr,
        nullptr, pxi16, pz16, DI, (long)LL*DI, DM, 2*DI, 0);

    // 2) depthwise causal conv + silu (fp16 out only)
    {
        long total = (long)2 * NB * (LL/4) * (DI/2);
        conv_silu_kernel<<<(unsigned)((total + 255) / 256), 256>>>(f_conv_w, f_conv_b, b_conv_w, b_conv_b);
    }

    // 3) x-projection: z=dir, M=8192, N=64(pad), K=768 -> fp32 g_xdbl
    hmma16<<<dim3(1, 64, 2), 256, HMMA16_SMEM>>>(
        pxch16, DI, (long)NB*LL*DI,
        pxpw16, pxpw16 + 64*DI, nullptr,
        pxdbl, nullptr, nullptr, XW, (long)NB*LL*XW, DI, XW, 1);

    // 4) delta; 4b) repack; 5) fused scan v3 + gate
    delta_gemm<<<dim3(DI/64, (NB*LL)/64, 2), 256>>>(f_dt_w, f_dt_b, b_dt_w, b_dt_b);
    repack_kernel<<<2048, 256>>>();
    scan_kernel<<<384, 128>>>(f_A_log, b_A_log, f_D, b_D);

    // 6) out-projection: z=dir, M=8192, N=384, K=768 -> fp16 ycat col halves
    hmma16<<<dim3(6, 64, 2), 256, HMMA16_SMEM>>>(
        pgate16, DI, (long)NB*LL*DI,
        poutw16, poutw16 + OUTW, nullptr,
        nullptr, pycat16, nullptr, 2*DM, (long)DM, DI, DM, 1);

    // 7) final 1x1 conv: M=8192, N=768, K=768, bias -> fp32 g_yc
    hmma16<<<dim3(12, 64, 1), 256, HMMA16_SMEM>>>(
        pycat16, 2*DM, 0L,
        pcw16, pcw16, c_b,
        pyc, nullptr, nullptr, 2*DM, 0L, 2*DM, 2*DM, 1);

    // 8) GLU + stats + normalize
    glu_kernel<<<dim3(48, 2), 256>>>();
    stats_kernel<<<1, 32>>>();
    norm_kernel<<<dim3(LL/32, DM/32, NB), 256>>>(gn_w, gn_b, out);
}